// round 1
// baseline (speedup 1.0000x reference)
#include <cuda_runtime.h>
#include <cuda_bf16.h>
#include <math.h>

// Problem constants
#define D      256
#define NE     8192
#define NS     8192
#define TOPK   16

// Device scratch (no allocations allowed in kernel_launch)
__device__ float g_q[NE * D];
__device__ float g_k[NS * D];
__device__ float g_v[NS * D];
__device__ float g_s[(size_t)NE * NS];   // 256 MB score matrix

// ---------------------------------------------------------------------------
// Unified fp32 GEMM:  C[i,j] = scale * sum_k Ael[i,k]*B[j,k] + bias[j]
//   Ael = A2 ? A.*A2 : A      (elementwise premultiply for the k-projection)
// Both operands are K-major with row stride = 256 (always true here).
// Tile: 128x128, TK=16, 256 threads, 8x8 per thread, double-buffered smem.
// dsel: 0->g_q, 1->g_k, 2->g_v, 3->g_s ; asel/bsel: 0->ext ptr, 1->g_q/g_k
// ---------------------------------------------------------------------------
__global__ void __launch_bounds__(256, 2)
gemm_kernel(const float* __restrict__ Aext, const float* __restrict__ A2,
            const float* __restrict__ Bext, const float* __restrict__ bias,
            int asel, int bsel, int dsel, int N, float scale)
{
    const float* A = asel ? g_q : Aext;
    const float* B = bsel ? g_k : Bext;
    float* C = (dsel == 0) ? g_q : (dsel == 1) ? g_k : (dsel == 2) ? g_v : g_s;
    const int ldc = N;

    const int bm = blockIdx.y;   // row tile
    const int bn = blockIdx.x;   // col tile

    __shared__ float As[2][16][128];
    __shared__ float Bs[2][16][128];

    const int tid = threadIdx.x;
    const int tx = tid & 15;         // 0..15 -> output cols tx*8..tx*8+7
    const int ty = tid >> 4;         // 0..15 -> output rows ty*8..ty*8+7

    const float* Ab  = A  + (size_t)(bm * 128) * D;
    const float* A2b = A2 ? (A2 + (size_t)(bm * 128) * D) : nullptr;
    const float* Bb  = B  + (size_t)(bn * 128) * D;

    float acc[8][8];
#pragma unroll
    for (int i = 0; i < 8; i++)
#pragma unroll
        for (int j = 0; j < 8; j++) acc[i][j] = 0.f;

    // Stage loader: 128 rows x 16 k per operand; each thread moves 2 float4
    // per operand.  f in [0,512): row = f>>2, kc = (f&3)*4.
    auto load_stage = [&](int buf, int k0) {
#pragma unroll
        for (int r = 0; r < 2; r++) {
            const int f   = tid + r * 256;
            const int row = f >> 2;
            const int kc  = (f & 3) * 4;
            float4 a = *(const float4*)(Ab + (size_t)row * D + k0 + kc);
            if (A2b) {
                float4 a2 = *(const float4*)(A2b + (size_t)row * D + k0 + kc);
                a.x *= a2.x; a.y *= a2.y; a.z *= a2.z; a.w *= a2.w;
            }
            As[buf][kc + 0][row] = a.x;
            As[buf][kc + 1][row] = a.y;
            As[buf][kc + 2][row] = a.z;
            As[buf][kc + 3][row] = a.w;
            float4 b = *(const float4*)(Bb + (size_t)row * D + k0 + kc);
            Bs[buf][kc + 0][row] = b.x;
            Bs[buf][kc + 1][row] = b.y;
            Bs[buf][kc + 2][row] = b.z;
            Bs[buf][kc + 3][row] = b.w;
        }
    };

    load_stage(0, 0);
    __syncthreads();

    const int nk = D / 16;  // 16 stages
    for (int kt = 0; kt < nk; kt++) {
        const int buf = kt & 1;
        if (kt + 1 < nk) load_stage(buf ^ 1, (kt + 1) * 16);
#pragma unroll
        for (int kk = 0; kk < 16; kk++) {
            float4 a0 = *(const float4*)&As[buf][kk][ty * 8];
            float4 a1 = *(const float4*)&As[buf][kk][ty * 8 + 4];
            float4 b0 = *(const float4*)&Bs[buf][kk][tx * 8];
            float4 b1 = *(const float4*)&Bs[buf][kk][tx * 8 + 4];
            float av[8] = {a0.x, a0.y, a0.z, a0.w, a1.x, a1.y, a1.z, a1.w};
            float bv[8] = {b0.x, b0.y, b0.z, b0.w, b1.x, b1.y, b1.z, b1.w};
#pragma unroll
            for (int i = 0; i < 8; i++)
#pragma unroll
                for (int j = 0; j < 8; j++)
                    acc[i][j] = fmaf(av[i], bv[j], acc[i][j]);
        }
        __syncthreads();
    }

    // Epilogue
    const int col0 = bn * 128 + tx * 8;
    float bia[8];
#pragma unroll
    for (int j = 0; j < 8; j++) bia[j] = bias ? bias[col0 + j] : 0.f;

#pragma unroll
    for (int i = 0; i < 8; i++) {
        const int row = bm * 128 + ty * 8 + i;
        float* crow = C + (size_t)row * ldc + col0;
        float4 w0, w1;
        w0.x = acc[i][0] * scale + bia[0];
        w0.y = acc[i][1] * scale + bia[1];
        w0.z = acc[i][2] * scale + bia[2];
        w0.w = acc[i][3] * scale + bia[3];
        w1.x = acc[i][4] * scale + bia[4];
        w1.y = acc[i][5] * scale + bia[5];
        w1.z = acc[i][6] * scale + bia[6];
        w1.w = acc[i][7] * scale + bia[7];
        *(float4*)(crow)     = w0;
        *(float4*)(crow + 4) = w1;
    }
}

// ---------------------------------------------------------------------------
// Top-16 + softmax + weighted v-aggregation. One block (256 threads) per ego
// row. Phase 1: per-thread streaming top-16 (threshold reject, register
// arrays via unrolled predicated ops). Phase 2: dump 256x16 candidates to
// smem, 16 rounds of block-wide argmax (tie-break: lower original index, to
// match jax.lax.top_k stability). Phase 3: softmax + gather-sum of v.
// ---------------------------------------------------------------------------
__global__ void __launch_bounds__(256)
topk_kernel(float* __restrict__ out)
{
    const int row = blockIdx.x;
    const int tid = threadIdx.x;
    const float* __restrict__ s = g_s + (size_t)row * NS;

    // Phase 1: local top-16 (unsorted, tracked min)
    float ls[TOPK];
    int   li[TOPK];
#pragma unroll
    for (int i = 0; i < TOPK; i++) { ls[i] = -INFINITY; li[i] = -1; }
    float lmin = -INFINITY;
    int   lminpos = 0;

    for (int c = tid; c < NS; c += 256) {
        const float v = s[c];
        if (v > lmin) {
#pragma unroll
            for (int i = 0; i < TOPK; i++)
                if (i == lminpos) { ls[i] = v; li[i] = c; }
            lmin = ls[0]; lminpos = 0;
#pragma unroll
            for (int i = 1; i < TOPK; i++)
                if (ls[i] < lmin) { lmin = ls[i]; lminpos = i; }
        }
    }

    // Phase 2: block merge
    __shared__ float ss[256 * TOPK];   // 16 KB
    __shared__ int   si[256 * TOPK];   // 16 KB
    __shared__ float rv[8];
    __shared__ int   ri[8], rp[8];
    __shared__ float wsc[TOPK];
    __shared__ int   wix[TOPK];

#pragma unroll
    for (int i = 0; i < TOPK; i++) {
        ss[tid * TOPK + i] = ls[i];
        si[tid * TOPK + i] = li[i];
    }
    __syncthreads();

    const int lane = tid & 31;
    const int wid  = tid >> 5;

    for (int t = 0; t < TOPK; t++) {
        // each thread scans its own 16 slots
        float bv = -INFINITY; int bi = 0x7fffffff; int bp = -1;
#pragma unroll
        for (int j = 0; j < TOPK; j++) {
            const int p = tid * TOPK + j;
            const float v = ss[p];
            const int   ix = si[p];
            if (v > bv || (v == bv && ix < bi)) { bv = v; bi = ix; bp = p; }
        }
        // warp reduce (prefer larger value, then lower index)
#pragma unroll
        for (int off = 16; off; off >>= 1) {
            float ov = __shfl_down_sync(0xffffffff, bv, off);
            int   oi = __shfl_down_sync(0xffffffff, bi, off);
            int   op = __shfl_down_sync(0xffffffff, bp, off);
            if (ov > bv || (ov == bv && oi < bi)) { bv = ov; bi = oi; bp = op; }
        }
        if (lane == 0) { rv[wid] = bv; ri[wid] = bi; rp[wid] = bp; }
        __syncthreads();
        if (tid == 0) {
            float fv = rv[0]; int fi = ri[0]; int fp = rp[0];
#pragma unroll
            for (int w = 1; w < 8; w++)
                if (rv[w] > fv || (rv[w] == fv && ri[w] < fi)) {
                    fv = rv[w]; fi = ri[w]; fp = rp[w];
                }
            wsc[t] = fv;
            wix[t] = fi;
            ss[fp] = -INFINITY;  // remove winner
        }
        __syncthreads();
    }

    // Phase 3: softmax over the 16 winners (redundant per-thread), then
    // each thread owns one output dim.
    float m = wsc[0];
#pragma unroll
    for (int i = 1; i < TOPK; i++) m = fmaxf(m, wsc[i]);
    float e[TOPK]; float sum = 0.f;
#pragma unroll
    for (int i = 0; i < TOPK; i++) { e[i] = expf(wsc[i] - m); sum += e[i]; }
    const float inv = 1.f / sum;

    float accv = 0.f;
#pragma unroll
    for (int i = 0; i < TOPK; i++)
        accv = fmaf(e[i] * inv, g_v[(size_t)wix[i] * D + tid], accv);

    out[(size_t)row * D + tid] = accv;
}

// ---------------------------------------------------------------------------
extern "C" void kernel_launch(void* const* d_in, const int* in_sizes, int n_in,
                              void* d_out, int out_size)
{
    const float* ego  = (const float*)d_in[0];
    const float* side = (const float*)d_in[1];
    const float* rel  = (const float*)d_in[2];
    const float* Wq   = (const float*)d_in[3];
    const float* bq   = (const float*)d_in[4];
    const float* Wk   = (const float*)d_in[5];
    const float* bk   = (const float*)d_in[6];
    const float* Wv   = (const float*)d_in[7];
    const float* bv   = (const float*)d_in[8];
    float* out = (float*)d_out;

    dim3 blk(256);
    // Projections: q = ego@Wq^T+bq ; k = (side.*rel)@Wk^T+bk ; v = side@Wv^T+bv
    gemm_kernel<<<dim3(2, 64), blk>>>(ego,  nullptr, Wq, bq, 0, 0, 0, 256, 1.f);
    gemm_kernel<<<dim3(2, 64), blk>>>(side, rel,     Wk, bk, 0, 0, 1, 256, 1.f);
    gemm_kernel<<<dim3(2, 64), blk>>>(side, nullptr, Wv, bv, 0, 0, 2, 256, 1.f);
    // Scores: s = (q @ k^T) / 16
    gemm_kernel<<<dim3(64, 64), blk>>>(nullptr, nullptr, nullptr, nullptr,
                                       1, 1, 3, 8192, 1.f / 16.f);
    // Top-16 + softmax + aggregate
    topk_kernel<<<NE, blk>>>(out);
}

// round 4
// speedup vs baseline: 1.5818x; 1.5818x over previous
#include <cuda_runtime.h>
#include <cuda_bf16.h>
#include <math.h>

// Problem constants
#define D      256
#define NE     8192
#define NS     8192
#define TOPK   16

// Device scratch (no allocations allowed in kernel_launch)
__device__ float g_q[NE * D];
__device__ float g_k[NS * D];
__device__ float g_v[NS * D];
__device__ float g_s[(size_t)NE * NS];   // 256 MB score matrix

// ---------------------------------------------------------------------------
// Unified fp32 GEMM:  C[i,j] = scale * sum_k Ael[i,k]*B[j,k] + bias[j]
//   Ael = A2 ? A.*A2 : A      (elementwise premultiply for the k-projection)
// Both operands are K-major with row stride = 256 (always true here).
// Tile: 128x128, TK=16, 256 threads, 8x8 per thread.
// Double-buffered smem stages + double-buffered register fragments (the
// kk+1 fragment loads issue while kk's 64 FFMAs execute, hiding LDS latency).
// dsel: 0->g_q, 1->g_k, 2->g_v, 3->g_s ; asel/bsel: 0->ext ptr, 1->g_q/g_k
// ---------------------------------------------------------------------------
__global__ void __launch_bounds__(256, 2)
gemm_kernel(const float* __restrict__ Aext, const float* __restrict__ A2,
            const float* __restrict__ Bext, const float* __restrict__ bias,
            int asel, int bsel, int dsel, int N, float scale)
{
    const float* A = asel ? g_q : Aext;
    const float* B = bsel ? g_k : Bext;
    float* C = (dsel == 0) ? g_q : (dsel == 1) ? g_k : (dsel == 2) ? g_v : g_s;
    const int ldc = N;

    const int bm = blockIdx.y;
    const int bn = blockIdx.x;

    __shared__ float As[2][16][128];
    __shared__ float Bs[2][16][128];

    const int tid = threadIdx.x;
    const int tx = tid & 15;
    const int ty = tid >> 4;

    const float* Ab  = A  + (size_t)(bm * 128) * D;
    const float* A2b = A2 ? (A2 + (size_t)(bm * 128) * D) : nullptr;
    const float* Bb  = B  + (size_t)(bn * 128) * D;

    float acc[8][8];
#pragma unroll
    for (int i = 0; i < 8; i++)
#pragma unroll
        for (int j = 0; j < 8; j++) acc[i][j] = 0.f;

    auto load_stage = [&](int buf, int k0) {
#pragma unroll
        for (int r = 0; r < 2; r++) {
            const int f   = tid + r * 256;
            const int row = f >> 2;
            const int kc  = (f & 3) * 4;
            float4 a = *(const float4*)(Ab + (size_t)row * D + k0 + kc);
            if (A2b) {
                float4 a2 = *(const float4*)(A2b + (size_t)row * D + k0 + kc);
                a.x *= a2.x; a.y *= a2.y; a.z *= a2.z; a.w *= a2.w;
            }
            As[buf][kc + 0][row] = a.x;
            As[buf][kc + 1][row] = a.y;
            As[buf][kc + 2][row] = a.z;
            As[buf][kc + 3][row] = a.w;
            float4 b = *(const float4*)(Bb + (size_t)row * D + k0 + kc);
            Bs[buf][kc + 0][row] = b.x;
            Bs[buf][kc + 1][row] = b.y;
            Bs[buf][kc + 2][row] = b.z;
            Bs[buf][kc + 3][row] = b.w;
        }
    };

    float ar[2][8], br[2][8];
    auto ldfrag = [&](int fb, int sb, int kk) {
        float4 a0 = *(const float4*)&As[sb][kk][ty * 8];
        float4 a1 = *(const float4*)&As[sb][kk][ty * 8 + 4];
        float4 b0 = *(const float4*)&Bs[sb][kk][tx * 8];
        float4 b1 = *(const float4*)&Bs[sb][kk][tx * 8 + 4];
        ar[fb][0] = a0.x; ar[fb][1] = a0.y; ar[fb][2] = a0.z; ar[fb][3] = a0.w;
        ar[fb][4] = a1.x; ar[fb][5] = a1.y; ar[fb][6] = a1.z; ar[fb][7] = a1.w;
        br[fb][0] = b0.x; br[fb][1] = b0.y; br[fb][2] = b0.z; br[fb][3] = b0.w;
        br[fb][4] = b1.x; br[fb][5] = b1.y; br[fb][6] = b1.z; br[fb][7] = b1.w;
    };

    load_stage(0, 0);
    __syncthreads();
    ldfrag(0, 0, 0);

    const int nk = D / 16;  // 16 stages
    for (int kt = 0; kt < nk; kt++) {
        const int sb = kt & 1;
        if (kt + 1 < nk) load_stage(sb ^ 1, (kt + 1) * 16);
#pragma unroll
        for (int kk = 0; kk < 16; kk++) {
            const int fb = kk & 1;
            if (kk + 1 < 16) ldfrag(fb ^ 1, sb, kk + 1);
#pragma unroll
            for (int i = 0; i < 8; i++)
#pragma unroll
                for (int j = 0; j < 8; j++)
                    acc[i][j] = fmaf(ar[fb][i], br[fb][j], acc[i][j]);
        }
        __syncthreads();
        if (kt + 1 < nk) ldfrag(0, sb ^ 1, 0);
    }

    const int col0 = bn * 128 + tx * 8;
    float bia[8];
#pragma unroll
    for (int j = 0; j < 8; j++) bia[j] = bias ? bias[col0 + j] : 0.f;

#pragma unroll
    for (int i = 0; i < 8; i++) {
        const int row = bm * 128 + ty * 8 + i;
        float* crow = C + (size_t)row * ldc + col0;
        float4 w0, w1;
        w0.x = acc[i][0] * scale + bia[0];
        w0.y = acc[i][1] * scale + bia[1];
        w0.z = acc[i][2] * scale + bia[2];
        w0.w = acc[i][3] * scale + bia[3];
        w1.x = acc[i][4] * scale + bia[4];
        w1.y = acc[i][5] * scale + bia[5];
        w1.z = acc[i][6] * scale + bia[6];
        w1.w = acc[i][7] * scale + bia[7];
        *(float4*)(crow)     = w0;
        *(float4*)(crow + 4) = w1;
    }
}

// ---------------------------------------------------------------------------
// Top-16 via exact radix select. One block (256 threads) per ego row.
//  1) load row as monotonic ordered uint keys into smem
//  2) 4x 8-bit radix passes -> exact key of the 16th-largest element
//  3) collect indices (> T, plus lowest-index ties == T), softmax, aggregate v
// Tie-break matches jax.lax.top_k (lower index wins among equal values).
// ---------------------------------------------------------------------------
__device__ __forceinline__ unsigned f2key(float f) {
    unsigned b = __float_as_uint(f);
    return (b & 0x80000000u) ? ~b : (b | 0x80000000u);
}
__device__ __forceinline__ float key2f(unsigned u) {
    unsigned b = (u & 0x80000000u) ? (u ^ 0x80000000u) : ~u;
    return __uint_as_float(b);
}

__global__ void __launch_bounds__(256)
topk_kernel(float* __restrict__ out)
{
    const int row = blockIdx.x;
    const int tid = threadIdx.x;
    const float* __restrict__ s = g_s + (size_t)row * NS;

    __shared__ unsigned keys[NS];      // 32 KB
    __shared__ int hist[256];
    __shared__ unsigned sh_cur;
    __shared__ int sh_want;
    __shared__ float wsc[TOPK];
    __shared__ int   wix[TOPK];
    __shared__ int   c_above, c_tie;
    __shared__ int   tie_idx[64];

    // 1) load + transform (coalesced float4 loads)
    for (int c = tid * 4; c < NS; c += 256 * 4) {
        float4 v = *(const float4*)(s + c);
        keys[c + 0] = f2key(v.x);
        keys[c + 1] = f2key(v.y);
        keys[c + 2] = f2key(v.z);
        keys[c + 3] = f2key(v.w);
    }
    if (tid == 0) { c_above = 0; c_tie = 0; }
    __syncthreads();

    // 2) radix passes: find exact 16th-largest key
    unsigned cur = 0, mask = 0;
    int want = TOPK;
#pragma unroll
    for (int pass = 0; pass < 4; pass++) {
        const int shift = 24 - pass * 8;
        hist[tid] = 0;
        __syncthreads();
        for (int c = tid; c < NS; c += 256) {
            const unsigned u = keys[c];
            if ((u & mask) == cur)
                atomicAdd(&hist[(u >> shift) & 255], 1);
        }
        __syncthreads();
        if (tid == 0) {
            int cum = 0, b = 255;
            for (b = 255; b >= 0; --b) {
                cum += hist[b];
                if (cum >= want) break;
            }
            sh_want = want - (cum - hist[b]);          // needed within bin b
            sh_cur  = cur | ((unsigned)b << shift);
        }
        __syncthreads();
        cur  = sh_cur;
        want = sh_want;
        mask |= (0xFFu << shift);
        __syncthreads();
    }
    const unsigned T = cur;     // key of the 16th-largest element
    // want = number of elements == T to include (>=1)

    // 3) collection
    for (int c = tid; c < NS; c += 256) {
        const unsigned u = keys[c];
        if (u > T) {
            const int p = atomicAdd(&c_above, 1);
            wix[p] = c;
            wsc[p] = key2f(u);
        } else if (u == T) {
            const int p = atomicAdd(&c_tie, 1);
            if (p < 64) tie_idx[p] = c;
        }
    }
    __syncthreads();
    if (tid == 0) {
        const int base = c_above;            // == TOPK - want
        int n = c_tie < 64 ? c_tie : 64;
        const float tv = key2f(T);
        for (int t = 0; t < want; t++) {
            int best = 0x7fffffff, bp = -1;
            for (int j = 0; j < n; j++)
                if (tie_idx[j] < best) { best = tie_idx[j]; bp = j; }
            wix[base + t] = best;
            wsc[base + t] = tv;
            tie_idx[bp] = 0x7fffffff;
        }
    }
    __syncthreads();

    // 4) softmax over 16 winners (redundant per thread) + v aggregation;
    //    each thread owns one output dim.
    float m = wsc[0];
#pragma unroll
    for (int i = 1; i < TOPK; i++) m = fmaxf(m, wsc[i]);
    float e[TOPK]; float sum = 0.f;
#pragma unroll
    for (int i = 0; i < TOPK; i++) { e[i] = expf(wsc[i] - m); sum += e[i]; }
    const float inv = 1.f / sum;

    float accv = 0.f;
#pragma unroll
    for (int i = 0; i < TOPK; i++)
        accv = fmaf(e[i] * inv, g_v[(size_t)wix[i] * D + tid], accv);

    out[(size_t)row * D + tid] = accv;
}

// ---------------------------------------------------------------------------
extern "C" void kernel_launch(void* const* d_in, const int* in_sizes, int n_in,
                              void* d_out, int out_size)
{
    const float* ego  = (const float*)d_in[0];
    const float* side = (const float*)d_in[1];
    const float* rel  = (const float*)d_in[2];
    const float* Wq   = (const float*)d_in[3];
    const float* bq   = (const float*)d_in[4];
    const float* Wk   = (const float*)d_in[5];
    const float* bk   = (const float*)d_in[6];
    const float* Wv   = (const float*)d_in[7];
    const float* bv   = (const float*)d_in[8];
    float* out = (float*)d_out;

    dim3 blk(256);
    gemm_kernel<<<dim3(2, 64), blk>>>(ego,  nullptr, Wq, bq, 0, 0, 0, 256, 1.f);
    gemm_kernel<<<dim3(2, 64), blk>>>(side, rel,     Wk, bk, 0, 0, 1, 256, 1.f);
    gemm_kernel<<<dim3(2, 64), blk>>>(side, nullptr, Wv, bv, 0, 0, 2, 256, 1.f);
    gemm_kernel<<<dim3(64, 64), blk>>>(nullptr, nullptr, nullptr, nullptr,
                                       1, 1, 3, 8192, 1.f / 16.f);
    topk_kernel<<<NE, blk>>>(out);
}

// round 6
// speedup vs baseline: 3.6846x; 2.3294x over previous
#include <cuda_runtime.h>
#include <cuda_bf16.h>
#include <math.h>
#include <stdint.h>

// Problem constants
#define D      256
#define NE     8192
#define NS     8192
#define TOPK   16
#define CAND   48     // approx top-C candidate target
#define CMAX   96     // candidate buffer cap

// Device scratch (no allocations allowed in kernel_launch)
__device__ float g_q[NE * D];
__device__ float g_k[NS * D];
__device__ float g_v[NS * D];
__device__ __align__(16) __nv_bfloat16 g_qh[NE * D];
__device__ __align__(16) __nv_bfloat16 g_kh[NS * D];
__device__ __align__(16) __nv_bfloat16 g_sb[(size_t)NE * NS];  // 128 MB approx scores

__device__ __forceinline__ uint32_t smem_u32(const void* p) {
    uint32_t a;
    asm("{ .reg .u64 t; cvta.to.shared.u64 t, %1; cvt.u32.u64 %0, t; }"
        : "=r"(a) : "l"(p));
    return a;
}

#define LDSM_X4(r0, r1, r2, r3, addr) \
    asm volatile("ldmatrix.sync.aligned.m8n8.x4.shared.b16 {%0,%1,%2,%3}, [%4];" \
                 : "=r"(r0), "=r"(r1), "=r"(r2), "=r"(r3) : "r"(addr))

#define MMA_BF16(c, a0, a1, a2, a3, b0, b1) \
    asm volatile("mma.sync.aligned.m16n8k16.row.col.f32.bf16.bf16.f32 " \
                 "{%0,%1,%2,%3}, {%4,%5,%6,%7}, {%8,%9}, {%0,%1,%2,%3};" \
                 : "+f"((c)[0]), "+f"((c)[1]), "+f"((c)[2]), "+f"((c)[3]) \
                 : "r"(a0), "r"(a1), "r"(a2), "r"(a3), "r"(b0), "r"(b1))

// ===========================================================================
// Projection GEMM (FFMA): C[i,j] = sum_k Ael[i,k]*W[j,k] + bias[j]
// dsel 0 -> fp32 g_q + bf16 g_qh ; dsel 1 -> fp32 g_k + bf16 g_kh (A.*A2)
// dsel 2 -> fp32 g_v
// ===========================================================================
__global__ void __launch_bounds__(256, 2)
proj_kernel(const float* __restrict__ A, const float* __restrict__ A2,
            const float* __restrict__ W, const float* __restrict__ bias,
            int dsel)
{
    const int bm = blockIdx.y;
    const int bn = blockIdx.x;

    __shared__ float As[2][16][128];
    __shared__ float Bs[2][16][128];

    const int tid = threadIdx.x;
    const int tx = tid & 15;
    const int ty = tid >> 4;

    const float* Ab  = A  + (size_t)(bm * 128) * D;
    const float* A2b = A2 ? (A2 + (size_t)(bm * 128) * D) : nullptr;
    const float* Bb  = W  + (size_t)(bn * 128) * D;

    float acc[8][8];
#pragma unroll
    for (int i = 0; i < 8; i++)
#pragma unroll
        for (int j = 0; j < 8; j++) acc[i][j] = 0.f;

    auto load_stage = [&](int buf, int k0) {
#pragma unroll
        for (int r = 0; r < 2; r++) {
            const int f   = tid + r * 256;
            const int row = f >> 2;
            const int kc  = (f & 3) * 4;
            float4 a = *(const float4*)(Ab + (size_t)row * D + k0 + kc);
            if (A2b) {
                float4 a2 = *(const float4*)(A2b + (size_t)row * D + k0 + kc);
                a.x *= a2.x; a.y *= a2.y; a.z *= a2.z; a.w *= a2.w;
            }
            As[buf][kc + 0][row] = a.x;
            As[buf][kc + 1][row] = a.y;
            As[buf][kc + 2][row] = a.z;
            As[buf][kc + 3][row] = a.w;
            float4 b = *(const float4*)(Bb + (size_t)row * D + k0 + kc);
            Bs[buf][kc + 0][row] = b.x;
            Bs[buf][kc + 1][row] = b.y;
            Bs[buf][kc + 2][row] = b.z;
            Bs[buf][kc + 3][row] = b.w;
        }
    };

    load_stage(0, 0);
    __syncthreads();

    const int nk = D / 16;
    for (int kt = 0; kt < nk; kt++) {
        const int buf = kt & 1;
        if (kt + 1 < nk) load_stage(buf ^ 1, (kt + 1) * 16);
#pragma unroll
        for (int kk = 0; kk < 16; kk++) {
            float4 a0 = *(const float4*)&As[buf][kk][ty * 8];
            float4 a1 = *(const float4*)&As[buf][kk][ty * 8 + 4];
            float4 b0 = *(const float4*)&Bs[buf][kk][tx * 8];
            float4 b1 = *(const float4*)&Bs[buf][kk][tx * 8 + 4];
            float av[8] = {a0.x, a0.y, a0.z, a0.w, a1.x, a1.y, a1.z, a1.w};
            float bv[8] = {b0.x, b0.y, b0.z, b0.w, b1.x, b1.y, b1.z, b1.w};
#pragma unroll
            for (int i = 0; i < 8; i++)
#pragma unroll
                for (int j = 0; j < 8; j++)
                    acc[i][j] = fmaf(av[i], bv[j], acc[i][j]);
        }
        __syncthreads();
    }

    const int col0 = bn * 128 + tx * 8;
    float bia[8];
#pragma unroll
    for (int j = 0; j < 8; j++) bia[j] = bias[col0 + j];

    float* Gf = (dsel == 0) ? g_q : (dsel == 1) ? g_k : g_v;
    __nv_bfloat16* Gh = (dsel == 0) ? g_qh : g_kh;

#pragma unroll
    for (int i = 0; i < 8; i++) {
        const int row = bm * 128 + ty * 8 + i;
        float v[8];
#pragma unroll
        for (int j = 0; j < 8; j++) v[j] = acc[i][j] + bia[j];
        float* crow = Gf + (size_t)row * D + col0;
        *(float4*)(crow)     = make_float4(v[0], v[1], v[2], v[3]);
        *(float4*)(crow + 4) = make_float4(v[4], v[5], v[6], v[7]);
        if (dsel != 2) {
            __nv_bfloat16* hrow = Gh + (size_t)row * D + col0;
#pragma unroll
            for (int j = 0; j < 4; j++)
                *(__nv_bfloat162*)(hrow + j * 2) =
                    __float22bfloat162_rn(make_float2(v[2 * j], v[2 * j + 1]));
        }
    }
}

// ===========================================================================
// Approx scores GEMM (bf16 HMMA mma.sync):  sb[i,j] ~= q[i] . k[j]  (no scale;
// monotonic, selection-only). Tile 128x128, 8 warps (warp tile 32x64),
// K chunked x32, double-buffered smem with 80-byte row stride (ldmatrix
// conflict-free), ldmatrix operand loads, m16n8k16 bf16->fp32 mma.
// ===========================================================================
__global__ void __launch_bounds__(256, 2)
approx_kernel()
{
    __shared__ __align__(16) char sm[40960];  // A0,B0,A1,B1 @ 10240 each
    const int tid  = threadIdx.x;
    const int lane = tid & 31;
    const int wid  = tid >> 5;
    const int wm   = wid >> 1;     // 0..3 -> rows wm*32
    const int wn   = wid & 1;      // 0..1 -> cols wn*64
    const int bm   = blockIdx.y;
    const int bn   = blockIdx.x;

    const uint32_t sb0 = smem_u32(sm);
    const uint32_t uA[2] = {sb0,         sb0 + 20480};
    const uint32_t uB[2] = {sb0 + 10240, sb0 + 30720};

    float acc[2][8][4];
#pragma unroll
    for (int mt = 0; mt < 2; mt++)
#pragma unroll
        for (int nt = 0; nt < 8; nt++)
#pragma unroll
            for (int r = 0; r < 4; r++) acc[mt][nt][r] = 0.f;

    // chunk loader: 2 tiles of 128 rows x 32 bf16 (64B/row), smem stride 80B
    auto load_chunk = [&](int c, int b) {
        const char* srcA = (const char*)g_qh + (size_t)(bm * 128) * 512 + c * 64;
        const char* srcB = (const char*)g_kh + (size_t)(bn * 128) * 512 + c * 64;
        char* dA = sm + (b ? 20480 : 0);
        char* dB = sm + (b ? 30720 : 10240);
#pragma unroll
        for (int t = 0; t < 4; t++) {
            const int i   = tid + t * 256;
            const int til = i >> 9;
            const int idx = i & 511;
            const int r   = idx >> 2;
            const int j   = idx & 3;
            const char* s = (til ? srcB : srcA) + (size_t)r * 512 + j * 16;
            char* d = (til ? dB : dA) + r * 80 + j * 16;
            *(uint4*)d = *(const uint4*)s;
        }
    };

    const int g  = lane >> 3;   // ldmatrix address group
    const int lr = lane & 7;

    load_chunk(0, 0);
    __syncthreads();

    for (int c = 0; c < 8; c++) {           // 8 chunks of k=32
        const int b = c & 1;
        if (c + 1 < 8) load_chunk(c + 1, b ^ 1);
#pragma unroll
        for (int ks = 0; ks < 2; ks++) {    // 2 k16 steps per chunk
            const int kb = ks * 32;
            uint32_t af[2][4], bf[8][2];
            // A frags: tiles (rows0-7,k0)(rows8-15,k0)(rows0-7,k+8)(rows8-15,k+8)
#pragma unroll
            for (int mt = 0; mt < 2; mt++) {
                const uint32_t addr = uA[b] +
                    (wm * 32 + mt * 16 + (g & 1) * 8 + lr) * 80 +
                    kb + (g >> 1) * 16;
                LDSM_X4(af[mt][0], af[mt][1], af[mt][2], af[mt][3], addr);
            }
            // B frags: per n16 pair: (n0-7,k0)(n0-7,k+8)(n8-15,k0)(n8-15,k+8)
#pragma unroll
            for (int np = 0; np < 4; np++) {
                const uint32_t addr = uB[b] +
                    (wn * 64 + np * 16 + (g >> 1) * 8 + lr) * 80 +
                    kb + (g & 1) * 16;
                uint32_t r0, r1, r2, r3;
                LDSM_X4(r0, r1, r2, r3, addr);
                bf[np * 2 + 0][0] = r0; bf[np * 2 + 0][1] = r1;
                bf[np * 2 + 1][0] = r2; bf[np * 2 + 1][1] = r3;
            }
#pragma unroll
            for (int mt = 0; mt < 2; mt++)
#pragma unroll
                for (int nt = 0; nt < 8; nt++)
                    MMA_BF16(acc[mt][nt], af[mt][0], af[mt][1], af[mt][2],
                             af[mt][3], bf[nt][0], bf[nt][1]);
        }
        __syncthreads();
    }

    // epilogue: fp32 acc -> bf16 scores
    const int gm0 = bm * 128 + wm * 32;
    const int gn0 = bn * 128 + wn * 64;
#pragma unroll
    for (int mt = 0; mt < 2; mt++)
#pragma unroll
        for (int nt = 0; nt < 8; nt++) {
            const int r0 = gm0 + mt * 16 + (lane >> 2);
            const int c0 = gn0 + nt * 8 + (lane & 3) * 2;
            float* a = acc[mt][nt];
            *(__nv_bfloat162*)&g_sb[(size_t)r0 * NS + c0] =
                __float22bfloat162_rn(make_float2(a[0], a[1]));
            *(__nv_bfloat162*)&g_sb[(size_t)(r0 + 8) * NS + c0] =
                __float22bfloat162_rn(make_float2(a[2], a[3]));
        }
}

// ===========================================================================
// Top-K: radix-select approx top-48 on 16-bit bf16 keys, exact fp32 rescore
// of <=96 candidates, exact top-16 (index tie-break), softmax, aggregate v.
// One block (256 threads) per ego row.
// ===========================================================================
__device__ __forceinline__ unsigned k16(unsigned h) {
    return ((h & 0x8000u) ? ~h : (h | 0x8000u)) & 0xFFFFu;
}

__global__ void __launch_bounds__(256)
topk_kernel(float* __restrict__ out)
{
    const int row  = blockIdx.x;
    const int tid  = threadIdx.x;
    const int lane = tid & 31;
    const int wid  = tid >> 5;

    __shared__ unsigned short keys[NS];   // 16 KB
    __shared__ int   hist[256];
    __shared__ float qs[D];
    __shared__ int   cidx[CMAX];
    __shared__ float rs[CMAX];
    __shared__ float wsc[TOPK];
    __shared__ int   wix[TOPK];
    __shared__ int   sh_b1, sh_want, sh_T, nc;

    // 1) load bf16 scores -> monotonic 16-bit keys
    const uint4* sp = (const uint4*)(g_sb + (size_t)row * NS);
    for (int i = tid; i < 1024; i += 256) {
        uint4 u = sp[i];
        const int c = i * 8;
        keys[c + 0] = (unsigned short)k16(u.x & 0xFFFFu);
        keys[c + 1] = (unsigned short)k16(u.x >> 16);
        keys[c + 2] = (unsigned short)k16(u.y & 0xFFFFu);
        keys[c + 3] = (unsigned short)k16(u.y >> 16);
        keys[c + 4] = (unsigned short)k16(u.z & 0xFFFFu);
        keys[c + 5] = (unsigned short)k16(u.z >> 16);
        keys[c + 6] = (unsigned short)k16(u.w & 0xFFFFu);
        keys[c + 7] = (unsigned short)k16(u.w >> 16);
    }
    hist[tid] = 0;
    if (tid == 0) nc = 0;
    qs[tid] = g_q[(size_t)row * D + tid];
    __syncthreads();

    // 2) radix pass 1 (high byte)
    for (int c = tid; c < NS; c += 256)
        atomicAdd(&hist[keys[c] >> 8], 1);
    __syncthreads();
    if (tid == 0) {
        int cum = 0, b = 255;
        for (; b >= 0; --b) { cum += hist[b]; if (cum >= CAND) break; }
        sh_b1 = b;
        sh_want = CAND - (cum - hist[b]);
    }
    __syncthreads();
    const int b1 = sh_b1;
    const int want = sh_want;
    hist[tid] = 0;
    __syncthreads();

    // 3) radix pass 2 (low byte within bucket b1)
    for (int c = tid; c < NS; c += 256) {
        const unsigned u = keys[c];
        if ((int)(u >> 8) == b1) atomicAdd(&hist[u & 255], 1);
    }
    __syncthreads();
    if (tid == 0) {
        int cum = 0, b = 255;
        for (; b >= 0; --b) { cum += hist[b]; if (cum >= want) break; }
        sh_T = (b1 << 8) | b;
    }
    __syncthreads();
    const unsigned T = (unsigned)sh_T;

    // 4) collect candidates (>= T), capped at CMAX
    for (int c = tid; c < NS; c += 256) {
        if (keys[c] >= T) {
            const int p = atomicAdd(&nc, 1);
            if (p < CMAX) cidx[p] = c;
        }
    }
    __syncthreads();
    const int Nc = nc < CMAX ? nc : CMAX;

    // 5) exact fp32 rescore: s = dot(q_row, k_cand) / 16
    for (int c = wid; c < Nc; c += 8) {
        const float* kr = g_k + (size_t)cidx[c] * D;
        float s = 0.f;
#pragma unroll
        for (int j = 0; j < 8; j++)
            s = fmaf(qs[lane * 8 + j], kr[lane * 8 + j], s);
#pragma unroll
        for (int o = 16; o; o >>= 1)
            s += __shfl_xor_sync(0xffffffff, s, o);
        if (lane == 0) rs[c] = s * (1.f / 16.f);
    }
    __syncthreads();

    // 6) exact top-16 (warp 0; lower index wins ties)
    if (wid == 0) {
        int used = 0;
        for (int t = 0; t < TOPK; t++) {
            float bv = -INFINITY; int bi = 0x7fffffff;
#pragma unroll
            for (int j = 0; j < 3; j++) {
                const int s = lane + 32 * j;
                if (s < Nc && !((used >> j) & 1)) {
                    const float v = rs[s];
                    const int  ix = cidx[s];
                    if (v > bv || (v == bv && ix < bi)) { bv = v; bi = ix; }
                }
            }
#pragma unroll
            for (int o = 16; o; o >>= 1) {
                const float ov = __shfl_xor_sync(0xffffffff, bv, o);
                const int   oi = __shfl_xor_sync(0xffffffff, bi, o);
                if (ov > bv || (ov == bv && oi < bi)) { bv = ov; bi = oi; }
            }
#pragma unroll
            for (int j = 0; j < 3; j++) {
                const int s = lane + 32 * j;
                if (s < Nc && cidx[s] == bi) used |= 1 << j;
            }
            if (lane == 0) { wsc[t] = bv; wix[t] = bi; }
        }
    }
    __syncthreads();

    // 7) softmax + v aggregation (thread owns one output dim)
    float m = wsc[0];
#pragma unroll
    for (int i = 1; i < TOPK; i++) m = fmaxf(m, wsc[i]);
    float e[TOPK]; float sum = 0.f;
#pragma unroll
    for (int i = 0; i < TOPK; i++) { e[i] = expf(wsc[i] - m); sum += e[i]; }
    const float inv = 1.f / sum;

    float accv = 0.f;
#pragma unroll
    for (int i = 0; i < TOPK; i++)
        accv = fmaf(e[i] * inv, g_v[(size_t)wix[i] * D + tid], accv);

    out[(size_t)row * D + tid] = accv;
}

// ---------------------------------------------------------------------------
extern "C" void kernel_launch(void* const* d_in, const int* in_sizes, int n_in,
                              void* d_out, int out_size)
{
    const float* ego  = (const float*)d_in[0];
    const float* side = (const float*)d_in[1];
    const float* rel  = (const float*)d_in[2];
    const float* Wq   = (const float*)d_in[3];
    const float* bq   = (const float*)d_in[4];
    const float* Wk   = (const float*)d_in[5];
    const float* bk   = (const float*)d_in[6];
    const float* Wv   = (const float*)d_in[7];
    const float* bv   = (const float*)d_in[8];
    float* out = (float*)d_out;

    dim3 blk(256);
    proj_kernel<<<dim3(2, 64), blk>>>(ego,  nullptr, Wq, bq, 0);
    proj_kernel<<<dim3(2, 64), blk>>>(side, rel,     Wk, bk, 1);
    proj_kernel<<<dim3(2, 64), blk>>>(side, nullptr, Wv, bv, 2);
    approx_kernel<<<dim3(64, 64), blk>>>();
    topk_kernel<<<NE, blk>>>(out);
}

// round 7
// speedup vs baseline: 4.0962x; 1.1117x over previous
#include <cuda_runtime.h>
#include <cuda_bf16.h>
#include <math.h>
#include <stdint.h>

// Problem constants
#define D      256
#define NE     8192
#define NS     8192
#define TOPK   16
#define CAND   48     // approx top-C candidate target
#define CMAX   96     // candidate buffer cap

// Device scratch (no allocations allowed in kernel_launch)
__device__ float g_q[NE * D];
__device__ float g_k[NS * D];
__device__ float g_v[NS * D];
__device__ __align__(16) __nv_bfloat16 g_qh[NE * D];
__device__ __align__(16) __nv_bfloat16 g_kh[NS * D];
__device__ __align__(16) __nv_bfloat16 g_sb[(size_t)NE * NS];  // 128 MB approx scores

__device__ __forceinline__ uint32_t smem_u32(const void* p) {
    uint32_t a;
    asm("{ .reg .u64 t; cvta.to.shared.u64 t, %1; cvt.u32.u64 %0, t; }"
        : "=r"(a) : "l"(p));
    return a;
}

#define LDSM_X4(r0, r1, r2, r3, addr) \
    asm volatile("ldmatrix.sync.aligned.m8n8.x4.shared.b16 {%0,%1,%2,%3}, [%4];" \
                 : "=r"(r0), "=r"(r1), "=r"(r2), "=r"(r3) : "r"(addr))

#define MMA_BF16(c, a0, a1, a2, a3, b0, b1) \
    asm volatile("mma.sync.aligned.m16n8k16.row.col.f32.bf16.bf16.f32 " \
                 "{%0,%1,%2,%3}, {%4,%5,%6,%7}, {%8,%9}, {%0,%1,%2,%3};" \
                 : "+f"((c)[0]), "+f"((c)[1]), "+f"((c)[2]), "+f"((c)[3]) \
                 : "r"(a0), "r"(a1), "r"(a2), "r"(a3), "r"(b0), "r"(b1))

// ===========================================================================
// Merged projection GEMMs (FFMA). gridDim.z selects:
//   z=0: q = ego@Wq^T+bq  -> fp32 g_q + bf16 g_qh
//   z=1: k = (side.*rel)@Wk^T+bk -> fp32 g_k + bf16 g_kh
//   z=2: v = side@Wv^T+bv -> fp32 g_v
// ===========================================================================
__global__ void __launch_bounds__(256, 2)
proj_kernel(const float* __restrict__ ego, const float* __restrict__ side,
            const float* __restrict__ rel,
            const float* __restrict__ Wq, const float* __restrict__ bq,
            const float* __restrict__ Wk, const float* __restrict__ bk,
            const float* __restrict__ Wv, const float* __restrict__ bv)
{
    const int z  = blockIdx.z;
    const float* A    = (z == 0) ? ego : side;
    const float* A2   = (z == 1) ? rel : nullptr;
    const float* W    = (z == 0) ? Wq : (z == 1) ? Wk : Wv;
    const float* bias = (z == 0) ? bq : (z == 1) ? bk : bv;

    const int bm = blockIdx.y;
    const int bn = blockIdx.x;

    __shared__ float As[2][16][128];
    __shared__ float Bs[2][16][128];

    const int tid = threadIdx.x;
    const int tx = tid & 15;
    const int ty = tid >> 4;

    const float* Ab  = A  + (size_t)(bm * 128) * D;
    const float* A2b = A2 ? (A2 + (size_t)(bm * 128) * D) : nullptr;
    const float* Bb  = W  + (size_t)(bn * 128) * D;

    float acc[8][8];
#pragma unroll
    for (int i = 0; i < 8; i++)
#pragma unroll
        for (int j = 0; j < 8; j++) acc[i][j] = 0.f;

    auto load_stage = [&](int buf, int k0) {
#pragma unroll
        for (int r = 0; r < 2; r++) {
            const int f   = tid + r * 256;
            const int row = f >> 2;
            const int kc  = (f & 3) * 4;
            float4 a = *(const float4*)(Ab + (size_t)row * D + k0 + kc);
            if (A2b) {
                float4 a2 = *(const float4*)(A2b + (size_t)row * D + k0 + kc);
                a.x *= a2.x; a.y *= a2.y; a.z *= a2.z; a.w *= a2.w;
            }
            As[buf][kc + 0][row] = a.x;
            As[buf][kc + 1][row] = a.y;
            As[buf][kc + 2][row] = a.z;
            As[buf][kc + 3][row] = a.w;
            float4 b = *(const float4*)(Bb + (size_t)row * D + k0 + kc);
            Bs[buf][kc + 0][row] = b.x;
            Bs[buf][kc + 1][row] = b.y;
            Bs[buf][kc + 2][row] = b.z;
            Bs[buf][kc + 3][row] = b.w;
        }
    };

    load_stage(0, 0);
    __syncthreads();

    const int nk = D / 16;
    for (int kt = 0; kt < nk; kt++) {
        const int buf = kt & 1;
        if (kt + 1 < nk) load_stage(buf ^ 1, (kt + 1) * 16);
#pragma unroll
        for (int kk = 0; kk < 16; kk++) {
            float4 a0 = *(const float4*)&As[buf][kk][ty * 8];
            float4 a1 = *(const float4*)&As[buf][kk][ty * 8 + 4];
            float4 b0 = *(const float4*)&Bs[buf][kk][tx * 8];
            float4 b1 = *(const float4*)&Bs[buf][kk][tx * 8 + 4];
            float av[8] = {a0.x, a0.y, a0.z, a0.w, a1.x, a1.y, a1.z, a1.w};
            float bvv[8] = {b0.x, b0.y, b0.z, b0.w, b1.x, b1.y, b1.z, b1.w};
#pragma unroll
            for (int i = 0; i < 8; i++)
#pragma unroll
                for (int j = 0; j < 8; j++)
                    acc[i][j] = fmaf(av[i], bvv[j], acc[i][j]);
        }
        __syncthreads();
    }

    const int col0 = bn * 128 + tx * 8;
    float bia[8];
#pragma unroll
    for (int j = 0; j < 8; j++) bia[j] = bias[col0 + j];

    float* Gf = (z == 0) ? g_q : (z == 1) ? g_k : g_v;
    __nv_bfloat16* Gh = (z == 0) ? g_qh : g_kh;

#pragma unroll
    for (int i = 0; i < 8; i++) {
        const int row = bm * 128 + ty * 8 + i;
        float v[8];
#pragma unroll
        for (int j = 0; j < 8; j++) v[j] = acc[i][j] + bia[j];
        float* crow = Gf + (size_t)row * D + col0;
        *(float4*)(crow)     = make_float4(v[0], v[1], v[2], v[3]);
        *(float4*)(crow + 4) = make_float4(v[4], v[5], v[6], v[7]);
        if (z != 2) {
            __nv_bfloat16* hrow = Gh + (size_t)row * D + col0;
#pragma unroll
            for (int j = 0; j < 4; j++)
                *(__nv_bfloat162*)(hrow + j * 2) =
                    __float22bfloat162_rn(make_float2(v[2 * j], v[2 * j + 1]));
        }
    }
}

// ===========================================================================
// Approx scores GEMM (bf16 HMMA mma.sync) — unchanged from R6 passing version.
// ===========================================================================
__global__ void __launch_bounds__(256, 2)
approx_kernel()
{
    __shared__ __align__(16) char sm[40960];  // A0,B0,A1,B1 @ 10240 each
    const int tid  = threadIdx.x;
    const int lane = tid & 31;
    const int wid  = tid >> 5;
    const int wm   = wid >> 1;
    const int wn   = wid & 1;
    const int bm   = blockIdx.y;
    const int bn   = blockIdx.x;

    const uint32_t sb0 = smem_u32(sm);
    const uint32_t uA[2] = {sb0,         sb0 + 20480};
    const uint32_t uB[2] = {sb0 + 10240, sb0 + 30720};

    float acc[2][8][4];
#pragma unroll
    for (int mt = 0; mt < 2; mt++)
#pragma unroll
        for (int nt = 0; nt < 8; nt++)
#pragma unroll
            for (int r = 0; r < 4; r++) acc[mt][nt][r] = 0.f;

    auto load_chunk = [&](int c, int b) {
        const char* srcA = (const char*)g_qh + (size_t)(bm * 128) * 512 + c * 64;
        const char* srcB = (const char*)g_kh + (size_t)(bn * 128) * 512 + c * 64;
        char* dA = sm + (b ? 20480 : 0);
        char* dB = sm + (b ? 30720 : 10240);
#pragma unroll
        for (int t = 0; t < 4; t++) {
            const int i   = tid + t * 256;
            const int til = i >> 9;
            const int idx = i & 511;
            const int r   = idx >> 2;
            const int j   = idx & 3;
            const char* s = (til ? srcB : srcA) + (size_t)r * 512 + j * 16;
            char* d = (til ? dB : dA) + r * 80 + j * 16;
            *(uint4*)d = *(const uint4*)s;
        }
    };

    const int g  = lane >> 3;
    const int lr = lane & 7;

    load_chunk(0, 0);
    __syncthreads();

    for (int c = 0; c < 8; c++) {
        const int b = c & 1;
        if (c + 1 < 8) load_chunk(c + 1, b ^ 1);
#pragma unroll
        for (int ks = 0; ks < 2; ks++) {
            const int kb = ks * 32;
            uint32_t af[2][4], bf[8][2];
#pragma unroll
            for (int mt = 0; mt < 2; mt++) {
                const uint32_t addr = uA[b] +
                    (wm * 32 + mt * 16 + (g & 1) * 8 + lr) * 80 +
                    kb + (g >> 1) * 16;
                LDSM_X4(af[mt][0], af[mt][1], af[mt][2], af[mt][3], addr);
            }
#pragma unroll
            for (int np = 0; np < 4; np++) {
                const uint32_t addr = uB[b] +
                    (wn * 64 + np * 16 + (g >> 1) * 8 + lr) * 80 +
                    kb + (g & 1) * 16;
                uint32_t r0, r1, r2, r3;
                LDSM_X4(r0, r1, r2, r3, addr);
                bf[np * 2 + 0][0] = r0; bf[np * 2 + 0][1] = r1;
                bf[np * 2 + 1][0] = r2; bf[np * 2 + 1][1] = r3;
            }
#pragma unroll
            for (int mt = 0; mt < 2; mt++)
#pragma unroll
                for (int nt = 0; nt < 8; nt++)
                    MMA_BF16(acc[mt][nt], af[mt][0], af[mt][1], af[mt][2],
                             af[mt][3], bf[nt][0], bf[nt][1]);
        }
        __syncthreads();
    }

    const int gm0 = bm * 128 + wm * 32;
    const int gn0 = bn * 128 + wn * 64;
#pragma unroll
    for (int mt = 0; mt < 2; mt++)
#pragma unroll
        for (int nt = 0; nt < 8; nt++) {
            const int r0 = gm0 + mt * 16 + (lane >> 2);
            const int c0 = gn0 + nt * 8 + (lane & 3) * 2;
            float* a = acc[mt][nt];
            *(__nv_bfloat162*)&g_sb[(size_t)r0 * NS + c0] =
                __float22bfloat162_rn(make_float2(a[0], a[1]));
            *(__nv_bfloat162*)&g_sb[(size_t)(r0 + 8) * NS + c0] =
                __float22bfloat162_rn(make_float2(a[2], a[3]));
        }
}

// ===========================================================================
// Top-K: register-resident keys + per-warp histograms + parallel suffix scan.
// Approx top-48 on 16-bit keys, exact fp32 rescore, exact top-16, softmax,
// aggregate v. One block (256 threads) per ego row.
// ===========================================================================
__device__ __forceinline__ unsigned k16(unsigned h) {
    return ((h & 0x8000u) ? ~h : (h | 0x8000u)) & 0xFFFFu;
}

__global__ void __launch_bounds__(256)
topk_kernel(float* __restrict__ out)
{
    const int row  = blockIdx.x;
    const int tid  = threadIdx.x;
    const int lane = tid & 31;
    const int wid  = tid >> 5;

    __shared__ int   whist[8][256];   // 8 KB per-warp histograms
    __shared__ int   suf[256];
    __shared__ float qs[D];
    __shared__ int   cidx[CMAX];
    __shared__ float rs[CMAX];
    __shared__ float wsc[TOPK];
    __shared__ int   wix[TOPK];
    __shared__ int   sh_b1, sh_above, sh_T, nc;

    // 1) load 32 bf16 scores per thread -> monotonic u16 keys in registers
    unsigned short lk[32];
    const uint4* sp = (const uint4*)(g_sb + (size_t)row * NS);
#pragma unroll
    for (int i = 0; i < 4; i++) {
        uint4 u = sp[tid + i * 256];
        unsigned w[4] = {u.x, u.y, u.z, u.w};
#pragma unroll
        for (int j = 0; j < 4; j++) {
            lk[i * 8 + j * 2 + 0] = (unsigned short)k16(w[j] & 0xFFFFu);
            lk[i * 8 + j * 2 + 1] = (unsigned short)k16(w[j] >> 16);
        }
    }
#pragma unroll
    for (int w = 0; w < 8; w++) whist[w][tid] = 0;
    qs[tid] = g_q[(size_t)row * D + tid];
    if (tid == 0) nc = 0;
    __syncthreads();

    // 2) pass 1 histogram (high byte) into per-warp hists
#pragma unroll
    for (int i = 0; i < 32; i++)
        atomicAdd(&whist[wid][lk[i] >> 8], 1);
    __syncthreads();
    {
        int h = 0;
#pragma unroll
        for (int w = 0; w < 8; w++) h += whist[w][tid];
        suf[tid] = h;
    }
    __syncthreads();
    // inclusive suffix scan (Hillis-Steele)
#pragma unroll
    for (int off = 1; off < 256; off <<= 1) {
        const int v = (tid + off < 256) ? suf[tid + off] : 0;
        __syncthreads();
        suf[tid] += v;
        __syncthreads();
    }
    if (suf[tid] >= CAND && (tid == 255 || suf[tid + 1] < CAND)) {
        sh_b1 = tid;
        sh_above = (tid == 255) ? 0 : suf[tid + 1];
    }
    whist[0][tid] = 0;   // reuse hist 0 for pass 2
    __syncthreads();
    const int b1   = sh_b1;
    const int want = CAND - sh_above;

    // 3) pass 2 histogram (low byte within bucket b1) — few entries, low contention
#pragma unroll
    for (int i = 0; i < 32; i++) {
        const unsigned u = lk[i];
        if ((int)(u >> 8) == b1) atomicAdd(&whist[0][u & 255], 1);
    }
    __syncthreads();
    suf[tid] = whist[0][tid];
    __syncthreads();
#pragma unroll
    for (int off = 1; off < 256; off <<= 1) {
        const int v = (tid + off < 256) ? suf[tid + off] : 0;
        __syncthreads();
        suf[tid] += v;
        __syncthreads();
    }
    if (suf[tid] >= want && (tid == 255 || suf[tid + 1] < want))
        sh_T = (b1 << 8) | tid;
    __syncthreads();
    const unsigned T = (unsigned)sh_T;

    // 4) collect candidate indices (key >= T)
#pragma unroll
    for (int i = 0; i < 4; i++)
#pragma unroll
        for (int jj = 0; jj < 8; jj++) {
            if (lk[i * 8 + jj] >= T) {
                const int p = atomicAdd(&nc, 1);
                if (p < CMAX) cidx[p] = (tid + i * 256) * 8 + jj;
            }
        }
    __syncthreads();
    const int Nc = nc < CMAX ? nc : CMAX;

    // 5) exact fp32 rescore: s = dot(q_row, k_cand) / 16  (stride-32 layout:
    //    conflict-free qs reads, coalesced k reads)
    for (int c = wid; c < Nc; c += 8) {
        const float* kr = g_k + (size_t)cidx[c] * D;
        float s = 0.f;
#pragma unroll
        for (int j = 0; j < 8; j++)
            s = fmaf(qs[lane + 32 * j], kr[lane + 32 * j], s);
#pragma unroll
        for (int o = 16; o; o >>= 1)
            s += __shfl_xor_sync(0xffffffff, s, o);
        if (lane == 0) rs[c] = s * (1.f / 16.f);
    }
    __syncthreads();

    // 6) exact top-16 (warp 0; lower index wins ties)
    if (wid == 0) {
        int used = 0;
        for (int t = 0; t < TOPK; t++) {
            float bv = -INFINITY; int bi = 0x7fffffff;
#pragma unroll
            for (int j = 0; j < 3; j++) {
                const int s = lane + 32 * j;
                if (s < Nc && !((used >> j) & 1)) {
                    const float v = rs[s];
                    const int  ix = cidx[s];
                    if (v > bv || (v == bv && ix < bi)) { bv = v; bi = ix; }
                }
            }
#pragma unroll
            for (int o = 16; o; o >>= 1) {
                const float ov = __shfl_xor_sync(0xffffffff, bv, o);
                const int   oi = __shfl_xor_sync(0xffffffff, bi, o);
                if (ov > bv || (ov == bv && oi < bi)) { bv = ov; bi = oi; }
            }
#pragma unroll
            for (int j = 0; j < 3; j++) {
                const int s = lane + 32 * j;
                if (s < Nc && cidx[s] == bi) used |= 1 << j;
            }
            if (lane == 0) { wsc[t] = bv; wix[t] = bi; }
        }
    }
    __syncthreads();

    // 7) softmax + v aggregation (thread owns one output dim)
    float m = wsc[0];
#pragma unroll
    for (int i = 1; i < TOPK; i++) m = fmaxf(m, wsc[i]);
    float e[TOPK]; float sum = 0.f;
#pragma unroll
    for (int i = 0; i < TOPK; i++) { e[i] = expf(wsc[i] - m); sum += e[i]; }
    const float inv = 1.f / sum;

    float accv = 0.f;
#pragma unroll
    for (int i = 0; i < TOPK; i++)
        accv = fmaf(e[i] * inv, g_v[(size_t)wix[i] * D + tid], accv);

    out[(size_t)row * D + tid] = accv;
}

// ---------------------------------------------------------------------------
extern "C" void kernel_launch(void* const* d_in, const int* in_sizes, int n_in,
                              void* d_out, int out_size)
{
    const float* ego  = (const float*)d_in[0];
    const float* side = (const float*)d_in[1];
    const float* rel  = (const float*)d_in[2];
    const float* Wq   = (const float*)d_in[3];
    const float* bq   = (const float*)d_in[4];
    const float* Wk   = (const float*)d_in[5];
    const float* bk   = (const float*)d_in[6];
    const float* Wv   = (const float*)d_in[7];
    const float* bv   = (const float*)d_in[8];
    float* out = (float*)d_out;

    dim3 blk(256);
    proj_kernel<<<dim3(2, 64, 3), blk>>>(ego, side, rel, Wq, bq, Wk, bk, Wv, bv);
    approx_kernel<<<dim3(64, 64), blk>>>();
    topk_kernel<<<NE, blk>>>(out);
}